// round 6
// baseline (speedup 1.0000x reference)
#include <cuda_runtime.h>
#include <cuda_bf16.h>
#include <cstdint>

#define BB 128
#define TT 2048
#define HH 512
#define MM (BB*TT)

// ---------------- device scratch (no allocations allowed) ----------------
__device__ __align__(16) __nv_bfloat16 g_Wh[HH*HH];
__device__ __align__(16) __nv_bfloat16 g_Wl[HH*HH];
__device__ __align__(16) float2 g_vb[HH];          // {v[o], bsum[o]*2*log2(e)}
__device__ float g_score[MM];
__device__ __align__(16) float g_cpart[8*BB*HH];

#define SW128(o) ((o) ^ (((o) >> 3) & 0x70))
#define TWO_LOG2E 2.885390081777927f

__device__ __forceinline__ uint32_t smem_u32(const void* p) {
    uint32_t a;
    asm("{ .reg .u64 t; cvta.to.shared.u64 t, %1; cvt.u32.u64 %0, t; }" : "=r"(a) : "l"(p));
    return a;
}
__device__ __forceinline__ uint32_t pack2bf(float lo, float hi) {
    uint32_t r;   // low-address element in low 16 bits
    asm("cvt.rn.bf16x2.f32 %0, %1, %2;" : "=r"(r) : "f"(hi), "f"(lo));
    return r;
}
__device__ __forceinline__ void ldsm4(uint32_t* r, uint32_t addr) {
    asm volatile("ldmatrix.sync.aligned.m8n8.x4.shared.b16 {%0,%1,%2,%3}, [%4];"
                 : "=r"(r[0]), "=r"(r[1]), "=r"(r[2]), "=r"(r[3]) : "r"(addr));
}
__device__ __forceinline__ void mma16816(float* c, const uint32_t* a, const uint32_t* b) {
    asm volatile("mma.sync.aligned.m16n8k16.row.col.f32.bf16.bf16.f32 "
                 "{%0,%1,%2,%3}, {%4,%5,%6,%7}, {%8,%9}, {%0,%1,%2,%3};"
                 : "+f"(c[0]), "+f"(c[1]), "+f"(c[2]), "+f"(c[3])
                 : "r"(a[0]), "r"(a[1]), "r"(a[2]), "r"(a[3]), "r"(b[0]), "r"(b[1]));
}
__device__ __forceinline__ void cpasync16(uint32_t saddr, const void* gptr) {
    asm volatile("cp.async.cg.shared.global [%0], [%1], 16;" :: "r"(saddr), "l"(gptr) : "memory");
}

// ---------------- K1: prep — Wsum split into bf16 hi/lo; vb table ----------------
__global__ void prep_kernel(const float* __restrict__ Wa_w, const float* __restrict__ Wa_b,
                            const float* __restrict__ Ua_w, const float* __restrict__ Ua_b,
                            const float* __restrict__ Va_w) {
    int i = blockIdx.x * blockDim.x + threadIdx.x;
    if (i < HH * HH) {
        float w = Wa_w[i] + Ua_w[i];
        __nv_bfloat16 h = __float2bfloat16_rn(w);
        g_Wh[i] = h;
        g_Wl[i] = __float2bfloat16_rn(w - __bfloat162float(h));
    }
    if (i < HH) {
        float b = Wa_b[i] + Ua_b[i];
        g_vb[i] = make_float2(Va_w[i], b * TWO_LOG2E);
    }
}

// ---------------- K2: fused score GEMM on legacy tensor cores ----------------
// score[m] = sum_o v[o] * tanh(bsum[o] + sum_k X[m,k]*Wsum[o,k])
// CTA: M=128, 2 passes of N=256, K=512 in 8 chunks of 64.
// Stage: Ah(16K) Al(16K) Bh(32K) Bl(32K) = 96KB, double buffered (192KB).

#define STAGE_SZ 98304
#define SM_DYN   (2*STAGE_SZ + 1024)

__device__ __forceinline__ void ldgA(const float* __restrict__ X, size_t m_base,
                                     int kc, float4* xr, int tid) {
#pragma unroll
    for (int i = 0; i < 8; i++) {
        int g  = tid + i * 256;         // 0..2047 float4 units (128 rows x 16)
        int m  = g >> 4;
        int k4 = (g & 15) << 2;
        xr[i] = *(const float4*)(X + (m_base + m) * HH + kc * 64 + k4);
    }
}

__device__ __forceinline__ void stA(uint32_t abase, int buf, const float4* xr, int tid) {
    const uint32_t Ah = abase + buf * STAGE_SZ;
    const uint32_t Al = Ah + 16384;
#pragma unroll
    for (int i = 0; i < 8; i++) {
        int g  = tid + i * 256;
        int m  = g >> 4;
        int k4 = (g & 15) << 2;
        float4 x = xr[i];
        uint32_t h0 = pack2bf(x.x, x.y);
        uint32_t h1 = pack2bf(x.z, x.w);
        float rx = x.x - __uint_as_float(h0 << 16);
        float ry = x.y - __uint_as_float(h0 & 0xffff0000u);
        float rz = x.z - __uint_as_float(h1 << 16);
        float rw = x.w - __uint_as_float(h1 & 0xffff0000u);
        uint32_t l0 = pack2bf(rx, ry);
        uint32_t l1 = pack2bf(rz, rw);
        uint32_t off = SW128(m * 128 + k4 * 2);
        asm volatile("st.shared.v2.b32 [%0], {%1,%2};" :: "r"(Ah + off), "r"(h0), "r"(h1) : "memory");
        asm volatile("st.shared.v2.b32 [%0], {%1,%2};" :: "r"(Al + off), "r"(l0), "r"(l1) : "memory");
    }
}

__device__ __forceinline__ void cpB(uint32_t abase, int buf, int nb, int kc, int tid) {
    const uint32_t Bh = abase + buf * STAGE_SZ + 32768;
    const uint32_t Bl = Bh + 32768;
    const char* gh = (const char*)g_Wh;
    const char* gl = (const char*)g_Wl;
#pragma unroll
    for (int i = 0; i < 8; i++) {
        int u  = tid + i * 256;         // 0..2047 (256 o-rows x 8 16B units)
        int o  = u >> 3;
        int uu = u & 7;
        size_t gbyte = ((size_t)(nb * 256 + o) * 64 + kc * 8 + uu) * 16;
        uint32_t off = SW128(o * 128 + uu * 16);
        cpasync16(Bh + off, gh + gbyte);
        cpasync16(Bl + off, gl + gbyte);
    }
}

__global__ __launch_bounds__(256, 1)
void score_kernel(const float* __restrict__ X) {
    extern __shared__ __align__(1024) char smem[];
    __shared__ float score_sm[128];
    const uint32_t sb = smem_u32(smem);
    const uint32_t abase = (sb + 1023u) & ~1023u;   // 1024-aligned stage base
    const int tid  = threadIdx.x;
    const int lane = tid & 31;
    const int wid  = tid >> 5;
    const int wm   = wid & 3;                        // m-warp 0..3 (32 rows each)
    const int wn   = wid >> 2;                       // n-warp 0..1 (128 cols each)
    const size_t m_base = (size_t)blockIdx.x * 128;

    if (tid < 128) score_sm[tid] = 0.0f;

    // ldmatrix per-lane offsets within swizzled 128B-row tiles
    const uint32_t xw = (uint32_t)((lane & 7) << 4);
    uint32_t aoff[2];
#pragma unroll
    for (int mf = 0; mf < 2; mf++) {
        int mrow = wm * 32 + mf * 16 + (lane & 15);
        aoff[mf] = mrow * 128 + ((lane >> 4) << 4);
    }
    uint32_t boff[8];
#pragma unroll
    for (int nf = 0; nf < 8; nf++) {
        int nrow = wn * 128 + nf * 16 + (lane & 7) + ((lane >> 4) << 3);
        boff[nf] = nrow * 128 + (((lane >> 3) & 1) << 4);
    }

    float4 xr[8];
    float c[2][16][4];

    for (int nb = 0; nb < 2; nb++) {
#pragma unroll
        for (int mf = 0; mf < 2; mf++)
#pragma unroll
            for (int j = 0; j < 16; j++)
#pragma unroll
                for (int q = 0; q < 4; q++) c[mf][j][q] = 0.0f;

        // stage chunk 0 into buf 0
        ldgA(X, m_base, 0, xr, tid);
        cpB(abase, 0, nb, 0, tid);
        stA(abase, 0, xr, tid);
        asm volatile("cp.async.commit_group;");
        asm volatile("cp.async.wait_group 0;" ::: "memory");
        __syncthreads();

        for (int kc = 0; kc < 8; kc++) {
            const int buf = kc & 1;
            if (kc < 7) {
                ldgA(X, m_base, kc + 1, xr, tid);
                cpB(abase, buf ^ 1, nb, kc + 1, tid);
                asm volatile("cp.async.commit_group;");
            }
            const uint32_t Ah = abase + buf * STAGE_SZ;
            const uint32_t Al = Ah + 16384;
            const uint32_t Bh = Ah + 32768;
            const uint32_t Bl = Ah + 65536;
#pragma unroll
            for (int k16 = 0; k16 < 4; k16++) {
                uint32_t ah[2][4], al[2][4], bb[8][4];
#pragma unroll
                for (int mf = 0; mf < 2; mf++) {
                    ldsm4(ah[mf], Ah + ((aoff[mf] + k16 * 32) ^ xw));
                    ldsm4(al[mf], Al + ((aoff[mf] + k16 * 32) ^ xw));
                }
#pragma unroll
                for (int nf = 0; nf < 8; nf++)
                    ldsm4(bb[nf], Bh + ((boff[nf] + k16 * 32) ^ xw));
#pragma unroll
                for (int mf = 0; mf < 2; mf++)
#pragma unroll
                    for (int nf = 0; nf < 8; nf++) {
                        mma16816(c[mf][2 * nf],     ah[mf], &bb[nf][0]);
                        mma16816(c[mf][2 * nf + 1], ah[mf], &bb[nf][2]);
                    }
#pragma unroll
                for (int mf = 0; mf < 2; mf++)
#pragma unroll
                    for (int nf = 0; nf < 8; nf++) {
                        mma16816(c[mf][2 * nf],     al[mf], &bb[nf][0]);
                        mma16816(c[mf][2 * nf + 1], al[mf], &bb[nf][2]);
                    }
#pragma unroll
                for (int nf = 0; nf < 8; nf++)
                    ldsm4(bb[nf], Bl + ((boff[nf] + k16 * 32) ^ xw));
#pragma unroll
                for (int mf = 0; mf < 2; mf++)
#pragma unroll
                    for (int nf = 0; nf < 8; nf++) {
                        mma16816(c[mf][2 * nf],     ah[mf], &bb[nf][0]);
                        mma16816(c[mf][2 * nf + 1], ah[mf], &bb[nf][2]);
                    }
            }
            if (kc < 7) {
                stA(abase, buf ^ 1, xr, tid);
                asm volatile("cp.async.wait_group 0;" ::: "memory");
            }
            __syncthreads();
        }

        // fused epilogue: score += v[o]*tanh(acc + b[o])
        const int quad = lane & 3;
#pragma unroll
        for (int mf = 0; mf < 2; mf++) {
            float s0 = 0.0f, s1 = 0.0f;
#pragma unroll
            for (int j = 0; j < 16; j++) {
#pragma unroll
                for (int col = 0; col < 2; col++) {
                    int o = nb * 256 + wn * 128 + j * 8 + quad * 2 + col;
                    float2 vbv = __ldg(&g_vb[o]);
                    float x0 = fmaf(c[mf][j][col],     TWO_LOG2E, vbv.y);
                    float x1 = fmaf(c[mf][j][col + 2], TWO_LOG2E, vbv.y);
                    float e0, e1, r0, r1;
                    asm("ex2.approx.f32 %0, %1;" : "=f"(e0) : "f"(x0));
                    asm("ex2.approx.f32 %0, %1;" : "=f"(e1) : "f"(x1));
                    asm("rcp.approx.f32 %0, %1;" : "=f"(r0) : "f"(e0 + 1.0f));
                    asm("rcp.approx.f32 %0, %1;" : "=f"(r1) : "f"(e1 + 1.0f));
                    s0 += vbv.x - 2.0f * vbv.x * r0;   // v*tanh
                    s1 += vbv.x - 2.0f * vbv.x * r1;
                }
            }
            s0 += __shfl_xor_sync(0xffffffffu, s0, 1);
            s0 += __shfl_xor_sync(0xffffffffu, s0, 2);
            s1 += __shfl_xor_sync(0xffffffffu, s1, 1);
            s1 += __shfl_xor_sync(0xffffffffu, s1, 2);
            if (quad == 0) {
                int r = wm * 32 + mf * 16 + (lane >> 2);
                atomicAdd(&score_sm[r], s0);
                atomicAdd(&score_sm[r + 8], s1);
            }
        }
        __syncthreads();
    }

    if (tid < 128) g_score[m_base + tid] = score_sm[tid];
}

// ---------------- K3: per-batch softmax over T ----------------
__global__ void softmax_kernel(float* __restrict__ aw_out) {
    __shared__ float sh[TT];
    __shared__ float red[256];
    const int b = blockIdx.x;
    const int tid = threadIdx.x;
    const float* s = g_score + (size_t)b * TT;

    float mx = -1e30f;
    for (int t = tid; t < TT; t += 256) {
        float v = s[t];
        sh[t] = v;
        mx = fmaxf(mx, v);
    }
    red[tid] = mx;
    __syncthreads();
    for (int o = 128; o > 0; o >>= 1) {
        if (tid < o) red[tid] = fmaxf(red[tid], red[tid + o]);
        __syncthreads();
    }
    mx = red[0];
    __syncthreads();

    float sum = 0.0f;
    for (int t = tid; t < TT; t += 256) {
        float e = __expf(sh[t] - mx);
        sh[t] = e;
        sum += e;
    }
    red[tid] = sum;
    __syncthreads();
    for (int o = 128; o > 0; o >>= 1) {
        if (tid < o) red[tid] += red[tid + o];
        __syncthreads();
    }
    float inv = 1.0f / red[0];
    for (int t = tid; t < TT; t += 256)
        aw_out[(size_t)b * TT + t] = sh[t] * inv;
}

// ---------------- K4: context partials (float4/thread), 8 T-chunks ----------------
__global__ void context_part_kernel(const float* __restrict__ X,
                                    const float* __restrict__ aw) {
    const int blk = blockIdx.x;           // b*8 + tb
    const int b  = blk >> 3;
    const int tb = blk & 7;
    const float4* xp = (const float4*)(X + (size_t)b * TT * HH + (size_t)tb * 256 * HH)
                       + threadIdx.x;     // thread covers h = tid*4..tid*4+3
    const float* a = aw + (size_t)b * TT + tb * 256;

    float4 acc = make_float4(0.f, 0.f, 0.f, 0.f);
#pragma unroll 8
    for (int t = 0; t < 256; t++) {
        float av = a[t];
        float4 x = xp[(size_t)t * 128];
        acc.x = fmaf(av, x.x, acc.x);
        acc.y = fmaf(av, x.y, acc.y);
        acc.z = fmaf(av, x.z, acc.z);
        acc.w = fmaf(av, x.w, acc.w);
    }
    ((float4*)g_cpart)[((size_t)tb * BB + b) * 128 + threadIdx.x] = acc;
}

__global__ void context_combine_kernel(float* __restrict__ ctx) {
    int i = blockIdx.x * blockDim.x + threadIdx.x;   // 0..BB*HH-1
    float s = 0.0f;
#pragma unroll
    for (int cpt = 0; cpt < 8; cpt++)
        s += g_cpart[cpt * BB * HH + i];
    ctx[i] = s;
}

// ---------------- launch ----------------
extern "C" void kernel_launch(void* const* d_in, const int* in_sizes, int n_in,
                              void* d_out, int out_size) {
    const float* X    = (const float*)d_in[0];
    const float* Wa_w = (const float*)d_in[1];
    const float* Wa_b = (const float*)d_in[2];
    const float* Ua_w = (const float*)d_in[3];
    const float* Ua_b = (const float*)d_in[4];
    const float* Va_w = (const float*)d_in[5];
    // d_in[6] (Va_b) unused: softmax is shift-invariant.
    (void)in_sizes; (void)n_in; (void)out_size;

    float* out = (float*)d_out;
    float* ctx = out;                 // [B, H]
    float* aw  = out + BB * HH;       // [B, T]

    cudaFuncSetAttribute(score_kernel, cudaFuncAttributeMaxDynamicSharedMemorySize, SM_DYN);

    prep_kernel<<<(HH * HH + 255) / 256, 256>>>(Wa_w, Wa_b, Ua_w, Ua_b, Va_w);
    score_kernel<<<MM / 128, 256, SM_DYN>>>(X);
    softmax_kernel<<<BB, 256>>>(aw);
    context_part_kernel<<<BB * 8, 128>>>(X, aw);
    context_combine_kernel<<<BB * HH / 256, 256>>>(ctx);
}

// round 8
// speedup vs baseline: 1.4838x; 1.4838x over previous
#include <cuda_runtime.h>
#include <cuda_bf16.h>
#include <cstdint>

#define BB 128
#define TT 2048
#define HH 512
#define MM (BB*TT)

// ---------------- device scratch (no allocations allowed) ----------------
__device__ __align__(16) __nv_bfloat16 g_Wh[HH*HH];
__device__ __align__(16) __nv_bfloat16 g_Wl[HH*HH];
__device__ __align__(16) float2 g_vb[HH];          // {v[o], bsum[o]*2*log2(e)}
__device__ float g_score[MM];
__device__ __align__(16) float g_cpart[16*BB*HH];

#define SW128(o) ((o) ^ (((o) >> 3) & 0x70))
#define TWO_LOG2E 2.885390081777927f

__device__ __forceinline__ uint32_t smem_u32(const void* p) {
    uint32_t a;
    asm("{ .reg .u64 t; cvta.to.shared.u64 t, %1; cvt.u32.u64 %0, t; }" : "=r"(a) : "l"(p));
    return a;
}
__device__ __forceinline__ uint32_t pack2bf(float lo, float hi) {
    uint32_t r;   // low-address element in low 16 bits
    asm("cvt.rn.bf16x2.f32 %0, %1, %2;" : "=r"(r) : "f"(hi), "f"(lo));
    return r;
}
__device__ __forceinline__ void ldsm4(uint32_t* r, uint32_t addr) {
    asm volatile("ldmatrix.sync.aligned.m8n8.x4.shared.b16 {%0,%1,%2,%3}, [%4];"
                 : "=r"(r[0]), "=r"(r[1]), "=r"(r[2]), "=r"(r[3]) : "r"(addr));
}
__device__ __forceinline__ void mma16816(float* c, const uint32_t* a, const uint32_t* b) {
    asm volatile("mma.sync.aligned.m16n8k16.row.col.f32.bf16.bf16.f32 "
                 "{%0,%1,%2,%3}, {%4,%5,%6,%7}, {%8,%9}, {%0,%1,%2,%3};"
                 : "+f"(c[0]), "+f"(c[1]), "+f"(c[2]), "+f"(c[3])
                 : "r"(a[0]), "r"(a[1]), "r"(a[2]), "r"(a[3]), "r"(b[0]), "r"(b[1]));
}
__device__ __forceinline__ void cpasync16(uint32_t saddr, const void* gptr) {
    asm volatile("cp.async.cg.shared.global [%0], [%1], 16;" :: "r"(saddr), "l"(gptr) : "memory");
}

// ---------------- K1: prep — Wsum split into bf16 hi/lo; vb table ----------------
__global__ void prep_kernel(const float* __restrict__ Wa_w, const float* __restrict__ Wa_b,
                            const float* __restrict__ Ua_w, const float* __restrict__ Ua_b,
                            const float* __restrict__ Va_w) {
    int i = blockIdx.x * blockDim.x + threadIdx.x;
    if (i < HH * HH) {
        float w = Wa_w[i] + Ua_w[i];
        __nv_bfloat16 h = __float2bfloat16_rn(w);
        g_Wh[i] = h;
        g_Wl[i] = __float2bfloat16_rn(w - __bfloat162float(h));
    }
    if (i < HH) {
        float b = Wa_b[i] + Ua_b[i];
        g_vb[i] = make_float2(Va_w[i], b * TWO_LOG2E);
    }
}

// ---------------- K2: fused score GEMM on legacy tensor cores ----------------
// score[m] = sum_o v[o] * tanh(bsum[o] + sum_k X[m,k]*Wsum[o,k])
// CTA: M=128, 4 passes of N=128, K=512 in 8 chunks of 64.
// SMEM/CTA (96KB): Ah(16K)+Al(16K) single-buffered; Bh+Bl 32KB x2 double-buffered.
// 2 CTAs/SM (launch_bounds 256,2 -> 128-reg cap).

#define SM_A_OFF  0
#define SM_B_OFF  32768
#define SM_DYN    (98304 + 1024)

// Inline A staging: LDG fp32 -> split bf16 hi/lo -> swizzled STS.
// Two half-phases of 4 float4 each to bound transient register pressure.
__device__ __forceinline__ void stA(const float* __restrict__ X, size_t m_base,
                                    int kc, uint32_t abase, int tid) {
    const uint32_t Ah = abase + SM_A_OFF;
    const uint32_t Al = Ah + 16384;
#pragma unroll 1
    for (int half = 0; half < 2; half++) {
        float4 t[4];
#pragma unroll
        for (int i = 0; i < 4; i++) {
            int g  = tid + (half * 4 + i) * 256;   // 0..2047 float4 units
            int m  = g >> 4;
            int k4 = (g & 15) << 2;
            t[i] = *(const float4*)(X + (m_base + m) * HH + kc * 64 + k4);
        }
#pragma unroll
        for (int i = 0; i < 4; i++) {
            int g  = tid + (half * 4 + i) * 256;
            int m  = g >> 4;
            int k4 = (g & 15) << 2;
            float4 x = t[i];
            uint32_t h0 = pack2bf(x.x, x.y);
            uint32_t h1 = pack2bf(x.z, x.w);
            float rx = x.x - __uint_as_float(h0 << 16);
            float ry = x.y - __uint_as_float(h0 & 0xffff0000u);
            float rz = x.z - __uint_as_float(h1 << 16);
            float rw = x.w - __uint_as_float(h1 & 0xffff0000u);
            uint32_t l0 = pack2bf(rx, ry);
            uint32_t l1 = pack2bf(rz, rw);
            uint32_t off = SW128(m * 128 + k4 * 2);
            asm volatile("st.shared.v2.b32 [%0], {%1,%2};" :: "r"(Ah + off), "r"(h0), "r"(h1) : "memory");
            asm volatile("st.shared.v2.b32 [%0], {%1,%2};" :: "r"(Al + off), "r"(l0), "r"(l1) : "memory");
        }
    }
}

__device__ __forceinline__ void cpB(uint32_t abase, int buf, int nb, int kc, int tid) {
    const uint32_t Bh = abase + SM_B_OFF + buf * 32768;
    const uint32_t Bl = Bh + 16384;
    const char* gh = (const char*)g_Wh;
    const char* gl = (const char*)g_Wl;
#pragma unroll
    for (int i = 0; i < 4; i++) {
        int u  = tid + i * 256;         // 0..1023 (128 o-rows x 8 16B units)
        int o  = u >> 3;
        int uu = u & 7;
        size_t gbyte = ((size_t)(nb * 128 + o) * 64 + kc * 8 + uu) * 16;
        uint32_t off = SW128(o * 128 + uu * 16);
        cpasync16(Bh + off, gh + gbyte);
        cpasync16(Bl + off, gl + gbyte);
    }
}

__global__ __launch_bounds__(256, 2)
void score_kernel(const float* __restrict__ X) {
    extern __shared__ __align__(1024) char smem[];
    __shared__ float score_sm[128];
    const uint32_t sb = smem_u32(smem);
    const uint32_t abase = (sb + 1023u) & ~1023u;   // 1024-aligned stage base
    const int tid  = threadIdx.x;
    const int lane = tid & 31;
    const int wid  = tid >> 5;
    const int wm   = wid & 3;                        // m-warp 0..3 (32 rows each)
    const int wn   = wid >> 2;                       // n-warp 0..1 (64 cols each)
    const size_t m_base = (size_t)blockIdx.x * 128;

    if (tid < 128) score_sm[tid] = 0.0f;

    // ldmatrix per-lane offsets within swizzled 128B-row tiles
    const uint32_t xw = (uint32_t)((lane & 7) << 4);
    uint32_t aoff[2];
#pragma unroll
    for (int mf = 0; mf < 2; mf++) {
        int mrow = wm * 32 + mf * 16 + (lane & 15);
        aoff[mf] = mrow * 128 + ((lane >> 4) << 4);
    }
    uint32_t boff[4];
#pragma unroll
    for (int nf = 0; nf < 4; nf++) {
        int nrow = wn * 64 + nf * 16 + (lane & 7) + ((lane >> 4) << 3);
        boff[nf] = nrow * 128 + (((lane >> 3) & 1) << 4);
    }

    float c[2][8][4];

    for (int nb = 0; nb < 4; nb++) {
#pragma unroll
        for (int mf = 0; mf < 2; mf++)
#pragma unroll
            for (int j = 0; j < 8; j++)
#pragma unroll
                for (int q = 0; q < 4; q++) c[mf][j][q] = 0.0f;

        // prefetch B chunk 0 into buf 0
        cpB(abase, 0, nb, 0, tid);
        asm volatile("cp.async.commit_group;");

        for (int kc = 0; kc < 8; kc++) {
            const int buf = kc & 1;
            __syncthreads();          // prev compute done: A free, B(buf^1) free
            if (kc < 7) {
                cpB(abase, buf ^ 1, nb, kc + 1, tid);
                asm volatile("cp.async.commit_group;");
            }
            stA(X, m_base, kc, abase, tid);
            if (kc < 7) asm volatile("cp.async.wait_group 1;" ::: "memory");
            else        asm volatile("cp.async.wait_group 0;" ::: "memory");
            __syncthreads();

            const uint32_t Ah = abase + SM_A_OFF;
            const uint32_t Al = Ah + 16384;
            const uint32_t Bh = abase + SM_B_OFF + buf * 32768;
            const uint32_t Bl = Bh + 16384;
#pragma unroll
            for (int k16 = 0; k16 < 4; k16++) {
                uint32_t ah[2][4], al[2][4], bb[4][4];
#pragma unroll
                for (int mf = 0; mf < 2; mf++) {
                    ldsm4(ah[mf], Ah + ((aoff[mf] + k16 * 32) ^ xw));
                    ldsm4(al[mf], Al + ((aoff[mf] + k16 * 32) ^ xw));
                }
#pragma unroll
                for (int nf = 0; nf < 4; nf++)
                    ldsm4(bb[nf], Bh + ((boff[nf] + k16 * 32) ^ xw));
#pragma unroll
                for (int mf = 0; mf < 2; mf++)
#pragma unroll
                    for (int nf = 0; nf < 4; nf++) {
                        mma16816(c[mf][2 * nf],     ah[mf], &bb[nf][0]);
                        mma16816(c[mf][2 * nf + 1], ah[mf], &bb[nf][2]);
                    }
#pragma unroll
                for (int mf = 0; mf < 2; mf++)
#pragma unroll
                    for (int nf = 0; nf < 4; nf++) {
                        mma16816(c[mf][2 * nf],     al[mf], &bb[nf][0]);
                        mma16816(c[mf][2 * nf + 1], al[mf], &bb[nf][2]);
                    }
#pragma unroll
                for (int nf = 0; nf < 4; nf++)
                    ldsm4(bb[nf], Bl + ((boff[nf] + k16 * 32) ^ xw));
#pragma unroll
                for (int mf = 0; mf < 2; mf++)
#pragma unroll
                    for (int nf = 0; nf < 4; nf++) {
                        mma16816(c[mf][2 * nf],     ah[mf], &bb[nf][0]);
                        mma16816(c[mf][2 * nf + 1], ah[mf], &bb[nf][2]);
                    }
            }
        }

        // fused epilogue: score += v[o]*tanh(acc + b[o])
        const int quad = lane & 3;
#pragma unroll
        for (int mf = 0; mf < 2; mf++) {
            float s0 = 0.0f, s1 = 0.0f;
#pragma unroll
            for (int j = 0; j < 8; j++) {
#pragma unroll
                for (int col = 0; col < 2; col++) {
                    int o = nb * 128 + wn * 64 + j * 8 + quad * 2 + col;
                    float2 vbv = __ldg(&g_vb[o]);
                    float x0 = fmaf(c[mf][j][col],     TWO_LOG2E, vbv.y);
                    float x1 = fmaf(c[mf][j][col + 2], TWO_LOG2E, vbv.y);
                    float e0, e1, r0, r1;
                    asm("ex2.approx.f32 %0, %1;" : "=f"(e0) : "f"(x0));
                    asm("ex2.approx.f32 %0, %1;" : "=f"(e1) : "f"(x1));
                    asm("rcp.approx.f32 %0, %1;" : "=f"(r0) : "f"(e0 + 1.0f));
                    asm("rcp.approx.f32 %0, %1;" : "=f"(r1) : "f"(e1 + 1.0f));
                    s0 += vbv.x - 2.0f * vbv.x * r0;   // v*tanh
                    s1 += vbv.x - 2.0f * vbv.x * r1;
                }
            }
            s0 += __shfl_xor_sync(0xffffffffu, s0, 1);
            s0 += __shfl_xor_sync(0xffffffffu, s0, 2);
            s1 += __shfl_xor_sync(0xffffffffu, s1, 1);
            s1 += __shfl_xor_sync(0xffffffffu, s1, 2);
            if (quad == 0) {
                int r = wm * 32 + mf * 16 + (lane >> 2);
                atomicAdd(&score_sm[r], s0);
                atomicAdd(&score_sm[r + 8], s1);
            }
        }
        __syncthreads();
    }

    if (tid < 128) g_score[m_base + tid] = score_sm[tid];
}

// ---------------- K3: per-batch softmax over T ----------------
__global__ void softmax_kernel(float* __restrict__ aw_out) {
    __shared__ float sh[TT];
    __shared__ float red[256];
    const int b = blockIdx.x;
    const int tid = threadIdx.x;
    const float* s = g_score + (size_t)b * TT;

    float mx = -1e30f;
    for (int t = tid; t < TT; t += 256) {
        float v = s[t];
        sh[t] = v;
        mx = fmaxf(mx, v);
    }
    red[tid] = mx;
    __syncthreads();
    for (int o = 128; o > 0; o >>= 1) {
        if (tid < o) red[tid] = fmaxf(red[tid], red[tid + o]);
        __syncthreads();
    }
    mx = red[0];
    __syncthreads();

    float sum = 0.0f;
    for (int t = tid; t < TT; t += 256) {
        float e = __expf(sh[t] - mx);
        sh[t] = e;
        sum += e;
    }
    red[tid] = sum;
    __syncthreads();
    for (int o = 128; o > 0; o >>= 1) {
        if (tid < o) red[tid] += red[tid + o];
        __syncthreads();
    }
    float inv = 1.0f / red[0];
    for (int t = tid; t < TT; t += 256)
        aw_out[(size_t)b * TT + t] = sh[t] * inv;
}

// ---------------- K4: context partials (float4/thread), 16 T-chunks ----------------
__global__ void context_part_kernel(const float* __restrict__ X,
                                    const float* __restrict__ aw) {
    const int blk = blockIdx.x;           // b*16 + tb
    const int b  = blk >> 4;
    const int tb = blk & 15;
    const float4* xp = (const float4*)(X + (size_t)b * TT * HH + (size_t)tb * 128 * HH)
                       + threadIdx.x;     // thread covers h = tid*4..tid*4+3
    const float* a = aw + (size_t)b * TT + tb * 128;

    float4 acc = make_float4(0.f, 0.f, 0.f, 0.f);
#pragma unroll 8
    for (int t = 0; t < 128; t++) {
        float av = a[t];
        float4 x = xp[(size_t)t * 128];
        acc.x = fmaf(av, x.x, acc.x);
        acc.y = fmaf(av, x.y, acc.y);
        acc.z = fmaf(av, x.z, acc.z);
        acc.w = fmaf(av, x.w, acc.w);
    }
    ((float4*)g_cpart)[((size_t)tb * BB + b) * 128 + threadIdx.x] = acc;
}

__global__ void context_combine_kernel(float* __restrict__ ctx) {
    int i = blockIdx.x * blockDim.x + threadIdx.x;   // 0..BB*HH-1
    float s = 0.0f;
#pragma unroll
    for (int cpt = 0; cpt < 16; cpt++)
        s += g_cpart[cpt * BB * HH + i];
    ctx[i] = s;
}

// ---------------- launch ----------------
extern "C" void kernel_launch(void* const* d_in, const int* in_sizes, int n_in,
                              void* d_out, int out_size) {
    const float* X    = (const float*)d_in[0];
    const float* Wa_w = (const float*)d_in[1];
    const float* Wa_b = (const float*)d_in[2];
    const float* Ua_w = (const float*)d_in[3];
    const float* Ua_b = (const float*)d_in[4];
    const float* Va_w = (const float*)d_in[5];
    // d_in[6] (Va_b) unused: softmax is shift-invariant.
    (void)in_sizes; (void)n_in; (void)out_size;

    float* out = (float*)d_out;
    float* ctx = out;                 // [B, H]
    float* aw  = out + BB * HH;       // [B, T]

    cudaFuncSetAttribute(score_kernel, cudaFuncAttributeMaxDynamicSharedMemorySize, SM_DYN);

    prep_kernel<<<(HH * HH + 255) / 256, 256>>>(Wa_w, Wa_b, Ua_w, Ua_b, Va_w);
    score_kernel<<<MM / 128, 256, SM_DYN>>>(X);
    softmax_kernel<<<BB, 256>>>(aw);
    context_part_kernel<<<BB * 16, 128>>>(X, aw);
    context_combine_kernel<<<BB * HH / 256, 256>>>(ctx);
}